// round 10
// baseline (speedup 1.0000x reference)
#include <cuda_runtime.h>
#include <cuda_fp16.h>
#include <stdint.h>

// ---------------------------------------------------------------------------
// Problem constants
// ---------------------------------------------------------------------------
#define Bb 8
#define Tt 2048
#define Mm 1024
#define Ff 2048
#define Ee 8
#define Ss 16384
#define CAP 2048
#define ECAP 16384
#define DROPPED 0x7FFFFFFF

// All single-term fp16 storage (hi):
//  dk, dr : fp16 [ECAP][1024]
//  h      : fp16 [ECAP][2048]
//  Wk',Wv',Wr' : fp16, N-major
__device__ __align__(128) __half g_dk_h[(size_t)ECAP * 1024];
__device__ __align__(128) __half g_dr_h[(size_t)ECAP * 1024];
__device__ __align__(128) __half g_h_h [(size_t)ECAP * 2048];
__device__ __align__(128) __half g_Wk_h[(size_t)Ee * 2048 * 1024];
__device__ __align__(128) __half g_Wv_h[(size_t)Ee * 1024 * 2048];
__device__ __align__(128) __half g_Wr_h[(size_t)Ee * 1024 * 1024];
__device__ float g_kv[(size_t)ECAP * Mm];
__device__ int   g_slot2tok[ECAP];
__device__ int   g_tok2slot[Ss];

// ---------------------------------------------------------------------------
// PTX helpers
// ---------------------------------------------------------------------------
__device__ __forceinline__ uint32_t smem_u32(const void* p) {
    uint32_t a;
    asm("{ .reg .u64 t; cvta.to.shared.u64 t, %1; cvt.u32.u64 %0, t; }" : "=r"(a) : "l"(p));
    return a;
}
__device__ __forceinline__ void cp16(uint32_t s, const void* g) {
    asm volatile("cp.async.cg.shared.global [%0], [%1], 16;" :: "r"(s), "l"(g) : "memory");
}
#define CP_COMMIT() asm volatile("cp.async.commit_group;" ::: "memory")
#define CP_WAIT2()  asm volatile("cp.async.wait_group 2;" ::: "memory")

#define LDSM_X4(r, a) \
    asm volatile("ldmatrix.sync.aligned.m8n8.x4.shared.b16 {%0,%1,%2,%3}, [%4];" \
        : "=r"((r)[0]), "=r"((r)[1]), "=r"((r)[2]), "=r"((r)[3]) : "r"(a))

__device__ __forceinline__ void mma_fp16(float* c, const uint32_t* a,
                                         uint32_t b0, uint32_t b1) {
    asm volatile(
        "mma.sync.aligned.m16n8k16.row.col.f32.f16.f16.f32 "
        "{%0,%1,%2,%3}, {%4,%5,%6,%7}, {%8,%9}, {%0,%1,%2,%3};"
        : "+f"(c[0]), "+f"(c[1]), "+f"(c[2]), "+f"(c[3])
        : "r"(a[0]), "r"(a[1]), "r"(a[2]), "r"(a[3]), "r"(b0), "r"(b1));
}

// ---------------------------------------------------------------------------
// Routing
// ---------------------------------------------------------------------------
__global__ void route_kernel(const int* __restrict__ tok) {
    __shared__ int cnt[256][8];
    const int t = threadIdx.x;
    for (int i = t; i < ECAP; i += 256) g_slot2tok[i] = -1;
    const int base = t * 64;
    int c[8] = {0,0,0,0,0,0,0,0};
    for (int i = 0; i < 64; ++i) { int e = (tok[base + i] * 5099) & 7; c[e]++; }
    #pragma unroll
    for (int e = 0; e < 8; ++e) cnt[t][e] = c[e];
    __syncthreads();
    if (t < 8) {
        int run = 0;
        for (int j = 0; j < 256; ++j) { int v = cnt[j][t]; cnt[j][t] = run; run += v; }
    }
    __syncthreads();
    int run[8];
    #pragma unroll
    for (int e = 0; e < 8; ++e) run[e] = cnt[t][e];
    for (int i = 0; i < 64; ++i) {
        int s = base + i;
        int e = (tok[s] * 5099) & 7;
        int pos = run[e]++;
        if (pos < CAP) { int slot = e * CAP + pos; g_tok2slot[s] = slot; g_slot2tok[slot] = s; }
        else g_tok2slot[s] = DROPPED;
    }
}

// ---------------------------------------------------------------------------
// Dispatch: token-shift mix; dk & dr fp16 hi only
// ---------------------------------------------------------------------------
__global__ void dispatch_kernel(const float* __restrict__ x,
                                const float* __restrict__ shift,
                                const float* __restrict__ maak,
                                const float* __restrict__ maar) {
    const int slot = blockIdx.x;
    const int j = threadIdx.x * 4;
    __half* rk = g_dk_h + (size_t)slot * 1024;
    __half* rr = g_dr_h + (size_t)slot * 1024;
    const int tokidx = g_slot2tok[slot];
    float4 dk, dr;
    if (tokidx < 0) {
        dk = dr = make_float4(0.f, 0.f, 0.f, 0.f);
    } else {
        const int b = tokidx / Tt;
        const int t = tokidx % Tt;
        float4 xv = *(const float4*)&x[(size_t)tokidx * Mm + j];
        float4 xp;
        if (t == 0) xp = *(const float4*)&shift[(size_t)b * Mm + j];
        else        xp = *(const float4*)&x[(size_t)(tokidx - 1) * Mm + j];
        float4 mk = *(const float4*)&maak[j];
        float4 mr = *(const float4*)&maar[j];
        float4 dx = make_float4(xp.x - xv.x, xp.y - xv.y, xp.z - xv.z, xp.w - xv.w);
        dk = make_float4(fmaf(dx.x, mk.x, xv.x), fmaf(dx.y, mk.y, xv.y),
                         fmaf(dx.z, mk.z, xv.z), fmaf(dx.w, mk.w, xv.w));
        dr = make_float4(fmaf(dx.x, mr.x, xv.x), fmaf(dx.y, mr.y, xv.y),
                         fmaf(dx.z, mr.z, xv.z), fmaf(dx.w, mr.w, xv.w));
    }
    *(__half2*)(rk + j)     = __halves2half2(__float2half(dk.x), __float2half(dk.y));
    *(__half2*)(rk + j + 2) = __halves2half2(__float2half(dk.z), __float2half(dk.w));
    *(__half2*)(rr + j)     = __halves2half2(__float2half(dr.x), __float2half(dr.y));
    *(__half2*)(rr + j + 2) = __halves2half2(__float2half(dr.z), __float2half(dr.w));
}

// ---------------------------------------------------------------------------
// Weight transpose: W [E][K][N] fp32 -> W' [E][N][K] fp16 (hi only)
// ---------------------------------------------------------------------------
__global__ void wconv_fp16_kernel(const float* __restrict__ W,
                                  __half* __restrict__ out, int K, int N) {
    __shared__ __half tile[64][33];
    const int e = blockIdx.z;
    const float* Wp = W + (size_t)e * K * N;
    __half* op = out + (size_t)e * N * K;
    const int k0 = blockIdx.y * 64, n0 = blockIdx.x * 32;
    const int tx = threadIdx.x, ty = threadIdx.y;   // (32, 8)
    #pragma unroll
    for (int i = 0; i < 8; ++i)
        tile[ty + i * 8][tx] = __float2half(Wp[(size_t)(k0 + ty + i * 8) * N + n0 + tx]);
    __syncthreads();
    #pragma unroll
    for (int j = 0; j < 4; ++j) {
        const int n = ty + j * 8;
        __half2 v = __halves2half2(tile[tx * 2][n], tile[tx * 2 + 1][n]);
        *(__half2*)&op[(size_t)(n0 + n) * K + k0 + tx * 2] = v;
    }
}

// ---------------------------------------------------------------------------
// Unified single-term fp16 HMMA GEMM.
// Block tile 256x128, 256 thr, 8 warps (4M x 2N), warp 64x64, acc 128 regs.
// Stage = A 16KB + B 8KB = 24KB, 4 stages (96KB), 1 CTA/SM.
// EPI 0: relu^2 -> fp16 into Cb. EPI 1: f32 copy to Cf.
// EPI 3: sigmoid * kv[slot] scattered to out[token] (fused combine).
// ---------------------------------------------------------------------------
constexpr int STAGE    = 24576;
constexpr int GEMM_SMEM = 4 * STAGE;   // 96 KB

template<int EPI, int TCH>
__global__ void __launch_bounds__(256, 1)
gemm_mma(const __half* __restrict__ Ag, const __half* __restrict__ Bg,
         float* __restrict__ Cf, __half* __restrict__ Cb,
         const float* __restrict__ KV, int N) {
    constexpr int K      = TCH * 32;
    constexpr int ROW_B  = 2 * K;       // bytes per row (both A and B)
    constexpr int BOFF   = 16384;       // B region offset within stage

    extern __shared__ __align__(1024) char smem[];
    const uint32_t sb = smem_u32(smem);
    const int tid = threadIdx.x;
    const int lane = tid & 31, warp = tid >> 5;
    const int wm = warp & 3, wn = warp >> 2;
    const int e = blockIdx.z;
    const int bm = blockIdx.y * 256, bn = blockIdx.x * 128;

    const char* A = (const char*)Ag + ((size_t)e * 2048 + bm) * ROW_B;
    const char* B = (const char*)Bg + ((size_t)e * N + bn) * ROW_B;

    // loader: A 256 rows (4 per thread), B 128 rows (2 per thread), 64B each
    const int lr = tid >> 2, lc = tid & 3;
    // swizzle invariant under +64-row steps: (row>>1)&3 unchanged
    const uint32_t swL = (uint32_t)(lr * 64 + ((lc ^ ((lr >> 1) & 3)) << 4));
    const uint32_t cbL = (uint32_t)(lc * 16);

    auto load_stage = [&](int st, int kt) {
        const int colB = kt * 64;
        const uint32_t b = sb + st * STAGE;
        #pragma unroll
        for (int i = 0; i < 4; ++i)
            cp16(b + swL + i * 4096,
                 A + (size_t)(lr + i * 64) * ROW_B + colB + cbL);
        #pragma unroll
        for (int i = 0; i < 2; ++i)
            cp16(b + BOFF + swL + i * 4096,
                 B + (size_t)(lr + i * 64) * ROW_B + colB + cbL);
    };

    // ldmatrix offsets: warp tile 64 rows (4 m16 frags, +16 rows = +1024B)
    const int rowA0 = wm * 64 + (lane & 15);
    const uint32_t aOff = (uint32_t)(rowA0 * 64 +
                          (((lane >> 4) ^ ((rowA0 >> 1) & 3)) << 4));
    const int rowB0 = wn * 64 + (lane & 7) + ((lane >> 4) << 3);
    const uint32_t bOff = (uint32_t)(rowB0 * 64 +
                          ((((lane >> 3) & 1) ^ ((rowB0 >> 1) & 3)) << 4));

    float acc[4][8][4];
    #pragma unroll
    for (int i = 0; i < 4; ++i)
        #pragma unroll
        for (int j = 0; j < 8; ++j)
            #pragma unroll
            for (int k = 0; k < 4; ++k) acc[i][j][k] = 0.f;

    load_stage(0, 0); CP_COMMIT();
    load_stage(1, 1); CP_COMMIT();
    load_stage(2, 2); CP_COMMIT();

    for (int kt = 0; kt < TCH; ++kt) {
        CP_WAIT2();
        __syncthreads();
        if (kt + 3 < TCH) load_stage((kt + 3) & 3, kt + 3);
        CP_COMMIT();

        const uint32_t stb = sb + (kt & 3) * STAGE;
        #pragma unroll
        for (int ks = 0; ks < 2; ++ks) {
            const uint32_t kx = ks * 32;
            uint32_t a[4][4];
            #pragma unroll
            for (int mi = 0; mi < 4; ++mi)
                LDSM_X4(a[mi], (stb + aOff + mi * 1024) ^ kx);
            uint32_t b[4][4];
            #pragma unroll
            for (int nf2 = 0; nf2 < 4; ++nf2)
                LDSM_X4(b[nf2], (stb + BOFF + bOff + nf2 * 1024) ^ kx);
            #pragma unroll
            for (int mi = 0; mi < 4; ++mi)
                #pragma unroll
                for (int nf2 = 0; nf2 < 4; ++nf2) {
                    mma_fp16(acc[mi][nf2 * 2 + 0], a[mi], b[nf2][0], b[nf2][1]);
                    mma_fp16(acc[mi][nf2 * 2 + 1], a[mi], b[nf2][2], b[nf2][3]);
                }
        }
    }

    // Epilogue
    #pragma unroll
    for (int mi = 0; mi < 4; ++mi) {
        #pragma unroll
        for (int nf = 0; nf < 8; ++nf) {
            const float* c = acc[mi][nf];
            const int col = bn + wn * 64 + nf * 8 + (lane & 3) * 2;
            const int row0 = bm + wm * 64 + mi * 16 + (lane >> 2);
            #pragma unroll
            for (int hh = 0; hh < 2; ++hh) {
                const int row = row0 + hh * 8;
                float v0 = c[hh * 2 + 0], v1 = c[hh * 2 + 1];
                if (EPI == 0) {
                    v0 = v0 > 0.f ? v0 * v0 : 0.f;
                    v1 = v1 > 0.f ? v1 * v1 : 0.f;
                    __half* p = Cb + ((size_t)e * 2048 + row) * (size_t)N + col;
                    *(__half2*)p = __halves2half2(__float2half(v0), __float2half(v1));
                } else if (EPI == 1) {
                    float* p = Cf + ((size_t)e * 2048 + row) * (size_t)N + col;
                    *(float2*)p = make_float2(v0, v1);
                } else {   // EPI == 3: fused sigmoid * kv -> out[token]
                    const int slot = e * 2048 + row;
                    const int tokidx = g_slot2tok[slot];
                    if (tokidx >= 0) {
                        float2 kv = *(const float2*)&KV[(size_t)slot * N + col];
                        v0 = kv.x / (1.f + __expf(-v0));
                        v1 = kv.y / (1.f + __expf(-v1));
                        *(float2*)&Cf[(size_t)tokidx * N + col] = make_float2(v0, v1);
                    }
                }
            }
        }
    }
}

// ---------------------------------------------------------------------------
// Zero-fill for dropped tokens; shift state
// ---------------------------------------------------------------------------
__global__ void zero_dropped_kernel(float* __restrict__ out) {
    const int s = blockIdx.x;
    if (g_tok2slot[s] != DROPPED) return;
    const int j = threadIdx.x * 4;
    *(float4*)&out[(size_t)s * Mm + j] = make_float4(0.f, 0.f, 0.f, 0.f);
}
__global__ void shift_kernel(const float* __restrict__ x, float* __restrict__ out) {
    const int b = blockIdx.x;
    const int j = threadIdx.x * 4;
    *(float4*)&out[(size_t)Ss * Mm + (size_t)b * Mm + j] =
        *(const float4*)&x[((size_t)b * Tt + (Tt - 1)) * Mm + j];
}

// ---------------------------------------------------------------------------
// Host
// ---------------------------------------------------------------------------
extern "C" void kernel_launch(void* const* d_in, const int* in_sizes, int n_in,
                              void* d_out, int out_size) {
    const float* x     = (const float*)d_in[0];
    const int*   tok   = (const int*)  d_in[1];
    const float* shift = (const float*)d_in[2];
    const float* maak  = (const float*)d_in[3];
    const float* maar  = (const float*)d_in[4];
    const float* Wk    = (const float*)d_in[5];
    const float* Wv    = (const float*)d_in[6];
    const float* Wr    = (const float*)d_in[7];
    float* out = (float*)d_out;

    void *dkh, *drh, *hh, *wkh, *wvh, *wrh, *kvp;
    cudaGetSymbolAddress(&dkh, g_dk_h);
    cudaGetSymbolAddress(&drh, g_dr_h);
    cudaGetSymbolAddress(&hh,  g_h_h);
    cudaGetSymbolAddress(&wkh, g_Wk_h);
    cudaGetSymbolAddress(&wvh, g_Wv_h);
    cudaGetSymbolAddress(&wrh, g_Wr_h);
    cudaGetSymbolAddress(&kvp, g_kv);

    cudaFuncSetAttribute((const void*)gemm_mma<0, 32>,
                         cudaFuncAttributeMaxDynamicSharedMemorySize, GEMM_SMEM);
    cudaFuncSetAttribute((const void*)gemm_mma<1, 64>,
                         cudaFuncAttributeMaxDynamicSharedMemorySize, GEMM_SMEM);
    cudaFuncSetAttribute((const void*)gemm_mma<3, 32>,
                         cudaFuncAttributeMaxDynamicSharedMemorySize, GEMM_SMEM);

    route_kernel<<<1, 256>>>(tok);
    dispatch_kernel<<<ECAP, 256>>>(x, shift, maak, maar);
    wconv_fp16_kernel<<<dim3(64, 16, 8), dim3(32, 8)>>>(Wk, (__half*)wkh, 1024, 2048);
    wconv_fp16_kernel<<<dim3(32, 32, 8), dim3(32, 8)>>>(Wv, (__half*)wvh, 2048, 1024);
    wconv_fp16_kernel<<<dim3(32, 16, 8), dim3(32, 8)>>>(Wr, (__half*)wrh, 1024, 1024);

    // h = relu^2(dk @ Wk): K=1024, N=2048
    gemm_mma<0, 32><<<dim3(16, 8, 8), 256, GEMM_SMEM>>>(
        (const __half*)dkh, (const __half*)wkh, nullptr, (__half*)hh, nullptr, 2048);
    // kv = h @ Wv: K=2048, N=1024
    gemm_mma<1, 64><<<dim3(8, 8, 8), 256, GEMM_SMEM>>>(
        (const __half*)hh, (const __half*)wvh, (float*)kvp, nullptr, nullptr, 1024);
    // out[token] = sigmoid(dr @ Wr) * kv (fused combine): K=1024, N=1024
    gemm_mma<3, 32><<<dim3(8, 8, 8), 256, GEMM_SMEM>>>(
        (const __half*)drh, (const __half*)wrh, out, nullptr,
        (const float*)kvp, 1024);

    zero_dropped_kernel<<<Ss, 256>>>(out);
    if ((size_t)out_size >= (size_t)Ss * Mm + (size_t)Bb * Mm)
        shift_kernel<<<Bb, 256>>>(x, out);
}

// round 11
// speedup vs baseline: 1.2661x; 1.2661x over previous
#include <cuda_runtime.h>
#include <cuda_fp16.h>
#include <stdint.h>

// ---------------------------------------------------------------------------
// Problem constants
// ---------------------------------------------------------------------------
#define Bb 8
#define Tt 2048
#define Mm 1024
#define Ff 2048
#define Ee 8
#define Ss 16384
#define CAP 2048
#define ECAP 16384
#define DROPPED 0x7FFFFFFF

// All single-term fp16 storage (hi):
__device__ __align__(128) __half g_dk_h[(size_t)ECAP * 1024];
__device__ __align__(128) __half g_dr_h[(size_t)ECAP * 1024];
__device__ __align__(128) __half g_h_h [(size_t)ECAP * 2048];
__device__ __align__(128) __half g_Wk_h[(size_t)Ee * 2048 * 1024];
__device__ __align__(128) __half g_Wv_h[(size_t)Ee * 1024 * 2048];
__device__ __align__(128) __half g_Wr_h[(size_t)Ee * 1024 * 1024];
__device__ float g_kv[(size_t)ECAP * Mm];
__device__ int   g_slot2tok[ECAP];
__device__ int   g_tok2slot[Ss];

// ---------------------------------------------------------------------------
// PTX helpers
// ---------------------------------------------------------------------------
__device__ __forceinline__ uint32_t smem_u32(const void* p) {
    uint32_t a;
    asm("{ .reg .u64 t; cvta.to.shared.u64 t, %1; cvt.u32.u64 %0, t; }" : "=r"(a) : "l"(p));
    return a;
}
__device__ __forceinline__ void cp16(uint32_t s, const void* g) {
    asm volatile("cp.async.cg.shared.global [%0], [%1], 16;" :: "r"(s), "l"(g) : "memory");
}
#define CP_COMMIT() asm volatile("cp.async.commit_group;" ::: "memory")
#define CP_WAIT2()  asm volatile("cp.async.wait_group 2;" ::: "memory")

#define LDSM_X4(r, a) \
    asm volatile("ldmatrix.sync.aligned.m8n8.x4.shared.b16 {%0,%1,%2,%3}, [%4];" \
        : "=r"((r)[0]), "=r"((r)[1]), "=r"((r)[2]), "=r"((r)[3]) : "r"(a))

__device__ __forceinline__ void mma_fp16(float* c, const uint32_t* a,
                                         uint32_t b0, uint32_t b1) {
    asm volatile(
        "mma.sync.aligned.m16n8k16.row.col.f32.f16.f16.f32 "
        "{%0,%1,%2,%3}, {%4,%5,%6,%7}, {%8,%9}, {%0,%1,%2,%3};"
        : "+f"(c[0]), "+f"(c[1]), "+f"(c[2]), "+f"(c[3])
        : "r"(a[0]), "r"(a[1]), "r"(a[2]), "r"(a[3]), "r"(b0), "r"(b1));
}

// ---------------------------------------------------------------------------
// Routing
// ---------------------------------------------------------------------------
__global__ void route_kernel(const int* __restrict__ tok) {
    __shared__ int cnt[256][8];
    const int t = threadIdx.x;
    for (int i = t; i < ECAP; i += 256) g_slot2tok[i] = -1;
    const int base = t * 64;
    int c[8] = {0,0,0,0,0,0,0,0};
    for (int i = 0; i < 64; ++i) { int e = (tok[base + i] * 5099) & 7; c[e]++; }
    #pragma unroll
    for (int e = 0; e < 8; ++e) cnt[t][e] = c[e];
    __syncthreads();
    if (t < 8) {
        int run = 0;
        for (int j = 0; j < 256; ++j) { int v = cnt[j][t]; cnt[j][t] = run; run += v; }
    }
    __syncthreads();
    int run[8];
    #pragma unroll
    for (int e = 0; e < 8; ++e) run[e] = cnt[t][e];
    for (int i = 0; i < 64; ++i) {
        int s = base + i;
        int e = (tok[s] * 5099) & 7;
        int pos = run[e]++;
        if (pos < CAP) { int slot = e * CAP + pos; g_tok2slot[s] = slot; g_slot2tok[slot] = s; }
        else g_tok2slot[s] = DROPPED;
    }
}

// ---------------------------------------------------------------------------
// Dispatch: token-shift mix; dk & dr fp16 hi only
// ---------------------------------------------------------------------------
__global__ void dispatch_kernel(const float* __restrict__ x,
                                const float* __restrict__ shift,
                                const float* __restrict__ maak,
                                const float* __restrict__ maar) {
    const int slot = blockIdx.x;
    const int j = threadIdx.x * 4;
    __half* rk = g_dk_h + (size_t)slot * 1024;
    __half* rr = g_dr_h + (size_t)slot * 1024;
    const int tokidx = g_slot2tok[slot];
    float4 dk, dr;
    if (tokidx < 0) {
        dk = dr = make_float4(0.f, 0.f, 0.f, 0.f);
    } else {
        const int b = tokidx / Tt;
        const int t = tokidx % Tt;
        float4 xv = *(const float4*)&x[(size_t)tokidx * Mm + j];
        float4 xp;
        if (t == 0) xp = *(const float4*)&shift[(size_t)b * Mm + j];
        else        xp = *(const float4*)&x[(size_t)(tokidx - 1) * Mm + j];
        float4 mk = *(const float4*)&maak[j];
        float4 mr = *(const float4*)&maar[j];
        float4 dx = make_float4(xp.x - xv.x, xp.y - xv.y, xp.z - xv.z, xp.w - xv.w);
        dk = make_float4(fmaf(dx.x, mk.x, xv.x), fmaf(dx.y, mk.y, xv.y),
                         fmaf(dx.z, mk.z, xv.z), fmaf(dx.w, mk.w, xv.w));
        dr = make_float4(fmaf(dx.x, mr.x, xv.x), fmaf(dx.y, mr.y, xv.y),
                         fmaf(dx.z, mr.z, xv.z), fmaf(dx.w, mr.w, xv.w));
    }
    *(__half2*)(rk + j)     = __halves2half2(__float2half(dk.x), __float2half(dk.y));
    *(__half2*)(rk + j + 2) = __halves2half2(__float2half(dk.z), __float2half(dk.w));
    *(__half2*)(rr + j)     = __halves2half2(__float2half(dr.x), __float2half(dr.y));
    *(__half2*)(rr + j + 2) = __halves2half2(__float2half(dr.z), __float2half(dr.w));
}

// ---------------------------------------------------------------------------
// Weight transpose: W [E][K][N] fp32 -> W' [E][N][K] fp16 (hi only)
// ---------------------------------------------------------------------------
__global__ void wconv_fp16_kernel(const float* __restrict__ W,
                                  __half* __restrict__ out, int K, int N) {
    __shared__ __half tile[64][33];
    const int e = blockIdx.z;
    const float* Wp = W + (size_t)e * K * N;
    __half* op = out + (size_t)e * N * K;
    const int k0 = blockIdx.y * 64, n0 = blockIdx.x * 32;
    const int tx = threadIdx.x, ty = threadIdx.y;   // (32, 8)
    #pragma unroll
    for (int i = 0; i < 8; ++i)
        tile[ty + i * 8][tx] = __float2half(Wp[(size_t)(k0 + ty + i * 8) * N + n0 + tx]);
    __syncthreads();
    #pragma unroll
    for (int j = 0; j < 4; ++j) {
        const int n = ty + j * 8;
        __half2 v = __halves2half2(tile[tx * 2][n], tile[tx * 2 + 1][n]);
        *(__half2*)&op[(size_t)(n0 + n) * K + k0 + tx * 2] = v;
    }
}

// ---------------------------------------------------------------------------
// Single-term fp16 HMMA GEMM (round-9 winning geometry).
// Block tile 128x128, 256 thr, 8 warps (4M x 2N), warp 32x64, 2 CTA/SM.
// Stage = A 8KB + B 8KB = 16KB, 4 stages (64KB).
// EPI 0: relu^2 -> fp16 into Cb. EPI 1: f32 copy to Cf.
// EPI 3: sigmoid * kv[slot] scattered to out[token] (fused combine).
// ---------------------------------------------------------------------------
constexpr int STAGE     = 16384;
constexpr int GEMM_SMEM = 4 * STAGE;   // 64 KB

template<int EPI, int TCH>
__global__ void __launch_bounds__(256, 2)
gemm_mma(const __half* __restrict__ Ag, const __half* __restrict__ Bg,
         float* __restrict__ Cf, __half* __restrict__ Cb,
         const float* __restrict__ KV, int N) {
    constexpr int K     = TCH * 32;
    constexpr int ROW_B = 2 * K;
    constexpr int BOFF  = 8192;

    extern __shared__ __align__(1024) char smem[];
    const uint32_t sb = smem_u32(smem);
    const int tid = threadIdx.x;
    const int lane = tid & 31, warp = tid >> 5;
    const int wm = warp & 3, wn = warp >> 2;
    const int e = blockIdx.z;
    const int bm = blockIdx.y * 128, bn = blockIdx.x * 128;

    const char* A = (const char*)Ag + ((size_t)e * 2048 + bm) * ROW_B;
    const char* B = (const char*)Bg + ((size_t)e * N + bn) * ROW_B;

    // loader: 128 rows x 64B per region, 2 rows/thread/region
    const int lr = tid >> 2, lc = tid & 3;
    const uint32_t sw0 = (uint32_t)(lr * 64 + ((lc ^ ((lr >> 1) & 3)) << 4));
    const uint32_t sw1 = (uint32_t)((lr + 64) * 64 + ((lc ^ (((lr + 64) >> 1) & 3)) << 4));
    const uint32_t cbL = (uint32_t)(lc * 16);

    auto load_stage = [&](int st, int kt) {
        const int colB = kt * 64;
        const uint32_t b = sb + st * STAGE;
        cp16(b + sw0,        A + (size_t)lr * ROW_B + colB + cbL);
        cp16(b + sw1,        A + (size_t)(lr + 64) * ROW_B + colB + cbL);
        cp16(b + BOFF + sw0, B + (size_t)lr * ROW_B + colB + cbL);
        cp16(b + BOFF + sw1, B + (size_t)(lr + 64) * ROW_B + colB + cbL);
    };

    const int rowA0 = wm * 32 + (lane & 15);
    const uint32_t aOff = (uint32_t)(rowA0 * 64 +
                          (((lane >> 4) ^ ((rowA0 >> 1) & 3)) << 4));
    const int rowB0 = wn * 64 + (lane & 7) + ((lane >> 4) << 3);
    const uint32_t bOff = (uint32_t)(rowB0 * 64 +
                          ((((lane >> 3) & 1) ^ ((rowB0 >> 1) & 3)) << 4));

    float acc[2][8][4];
    #pragma unroll
    for (int i = 0; i < 2; ++i)
        #pragma unroll
        for (int j = 0; j < 8; ++j)
            #pragma unroll
            for (int k = 0; k < 4; ++k) acc[i][j][k] = 0.f;

    load_stage(0, 0); CP_COMMIT();
    load_stage(1, 1); CP_COMMIT();
    load_stage(2, 2); CP_COMMIT();

    for (int kt = 0; kt < TCH; ++kt) {
        CP_WAIT2();
        __syncthreads();
        if (kt + 3 < TCH) load_stage((kt + 3) & 3, kt + 3);
        CP_COMMIT();

        const uint32_t stb = sb + (kt & 3) * STAGE;
        #pragma unroll
        for (int ks = 0; ks < 2; ++ks) {
            const uint32_t kx = ks * 32;
            uint32_t a[2][4];
            #pragma unroll
            for (int mi = 0; mi < 2; ++mi)
                LDSM_X4(a[mi], (stb + aOff + mi * 1024) ^ kx);
            uint32_t b[4][4];
            #pragma unroll
            for (int nf2 = 0; nf2 < 4; ++nf2)
                LDSM_X4(b[nf2], (stb + BOFF + bOff + nf2 * 1024) ^ kx);
            #pragma unroll
            for (int mi = 0; mi < 2; ++mi)
                #pragma unroll
                for (int nf2 = 0; nf2 < 4; ++nf2) {
                    mma_fp16(acc[mi][nf2 * 2 + 0], a[mi], b[nf2][0], b[nf2][1]);
                    mma_fp16(acc[mi][nf2 * 2 + 1], a[mi], b[nf2][2], b[nf2][3]);
                }
        }
    }

    // Epilogue
    #pragma unroll
    for (int mi = 0; mi < 2; ++mi) {
        #pragma unroll
        for (int nf = 0; nf < 8; ++nf) {
            const float* c = acc[mi][nf];
            const int col = bn + wn * 64 + nf * 8 + (lane & 3) * 2;
            const int row0 = bm + wm * 32 + mi * 16 + (lane >> 2);
            #pragma unroll
            for (int hh = 0; hh < 2; ++hh) {
                const int row = row0 + hh * 8;
                float v0 = c[hh * 2 + 0], v1 = c[hh * 2 + 1];
                if (EPI == 0) {
                    v0 = v0 > 0.f ? v0 * v0 : 0.f;
                    v1 = v1 > 0.f ? v1 * v1 : 0.f;
                    __half* p = Cb + ((size_t)e * 2048 + row) * (size_t)N + col;
                    *(__half2*)p = __halves2half2(__float2half(v0), __float2half(v1));
                } else if (EPI == 1) {
                    float* p = Cf + ((size_t)e * 2048 + row) * (size_t)N + col;
                    *(float2*)p = make_float2(v0, v1);
                } else {   // EPI == 3: fused sigmoid * kv -> out[token]
                    const int slot = e * 2048 + row;
                    const int tokidx = g_slot2tok[slot];
                    if (tokidx >= 0) {
                        float2 kv = *(const float2*)&KV[(size_t)slot * N + col];
                        v0 = kv.x / (1.f + __expf(-v0));
                        v1 = kv.y / (1.f + __expf(-v1));
                        *(float2*)&Cf[(size_t)tokidx * N + col] = make_float2(v0, v1);
                    }
                }
            }
        }
    }
}

// ---------------------------------------------------------------------------
// Zero-fill for dropped tokens; shift state
// ---------------------------------------------------------------------------
__global__ void zero_dropped_kernel(float* __restrict__ out) {
    const int s = blockIdx.x;
    if (g_tok2slot[s] != DROPPED) return;
    const int j = threadIdx.x * 4;
    *(float4*)&out[(size_t)s * Mm + j] = make_float4(0.f, 0.f, 0.f, 0.f);
}
__global__ void shift_kernel(const float* __restrict__ x, float* __restrict__ out) {
    const int b = blockIdx.x;
    const int j = threadIdx.x * 4;
    *(float4*)&out[(size_t)Ss * Mm + (size_t)b * Mm + j] =
        *(const float4*)&x[((size_t)b * Tt + (Tt - 1)) * Mm + j];
}

// ---------------------------------------------------------------------------
// Host
// ---------------------------------------------------------------------------
extern "C" void kernel_launch(void* const* d_in, const int* in_sizes, int n_in,
                              void* d_out, int out_size) {
    const float* x     = (const float*)d_in[0];
    const int*   tok   = (const int*)  d_in[1];
    const float* shift = (const float*)d_in[2];
    const float* maak  = (const float*)d_in[3];
    const float* maar  = (const float*)d_in[4];
    const float* Wk    = (const float*)d_in[5];
    const float* Wv    = (const float*)d_in[6];
    const float* Wr    = (const float*)d_in[7];
    float* out = (float*)d_out;

    void *dkh, *drh, *hh, *wkh, *wvh, *wrh, *kvp;
    cudaGetSymbolAddress(&dkh, g_dk_h);
    cudaGetSymbolAddress(&drh, g_dr_h);
    cudaGetSymbolAddress(&hh,  g_h_h);
    cudaGetSymbolAddress(&wkh, g_Wk_h);
    cudaGetSymbolAddress(&wvh, g_Wv_h);
    cudaGetSymbolAddress(&wrh, g_Wr_h);
    cudaGetSymbolAddress(&kvp, g_kv);

    cudaFuncSetAttribute((const void*)gemm_mma<0, 32>,
                         cudaFuncAttributeMaxDynamicSharedMemorySize, GEMM_SMEM);
    cudaFuncSetAttribute((const void*)gemm_mma<1, 64>,
                         cudaFuncAttributeMaxDynamicSharedMemorySize, GEMM_SMEM);
    cudaFuncSetAttribute((const void*)gemm_mma<3, 32>,
                         cudaFuncAttributeMaxDynamicSharedMemorySize, GEMM_SMEM);

    route_kernel<<<1, 256>>>(tok);
    dispatch_kernel<<<ECAP, 256>>>(x, shift, maak, maar);
    wconv_fp16_kernel<<<dim3(64, 16, 8), dim3(32, 8)>>>(Wk, (__half*)wkh, 1024, 2048);
    wconv_fp16_kernel<<<dim3(32, 32, 8), dim3(32, 8)>>>(Wv, (__half*)wvh, 2048, 1024);
    wconv_fp16_kernel<<<dim3(32, 16, 8), dim3(32, 8)>>>(Wr, (__half*)wrh, 1024, 1024);

    // h = relu^2(dk @ Wk): K=1024, N=2048
    gemm_mma<0, 32><<<dim3(16, 16, 8), 256, GEMM_SMEM>>>(
        (const __half*)dkh, (const __half*)wkh, nullptr, (__half*)hh, nullptr, 2048);
    // kv = h @ Wv: K=2048, N=1024
    gemm_mma<1, 64><<<dim3(8, 16, 8), 256, GEMM_SMEM>>>(
        (const __half*)hh, (const __half*)wvh, (float*)kvp, nullptr, nullptr, 1024);
    // out[token] = sigmoid(dr @ Wr) * kv (fused combine): K=1024, N=1024
    gemm_mma<3, 32><<<dim3(8, 16, 8), 256, GEMM_SMEM>>>(
        (const __half*)drh, (const __half*)wrh, out, nullptr,
        (const float*)kvp, 1024);

    zero_dropped_kernel<<<Ss, 256>>>(out);
    if ((size_t)out_size >= (size_t)Ss * Mm + (size_t)Bb * Mm)
        shift_kernel<<<Bb, 256>>>(x, out);
}